// round 2
// baseline (speedup 1.0000x reference)
#include <cuda_runtime.h>

// CLUBLoss: fixed shapes
//   x        : (B=16, D=512, H=32, W=32) f32
//   p_mu     : (N=16384, D=512) f32   with n = b*H*W + h*W + w
//   p_logvar : (N=16384, D=512) f32
// out = mean_i [ -0.5 * sum_d (x_i^2 - 2*mu*(x_i - m1_d) - m2_d) * exp(-logvar) ]
// m1_d = mean_j flat_x[j][d], m2_d = mean_j flat_x[j][d]^2.

#define DI      512
#define BB      16
#define HH      32
#define WW      32
#define NN      (BB * HH * WW)      // 16384
#define SPATIAL (HH * WW)           // 1024
#define DH      256                 // d-columns per loss tile
#define NBLK_B  1024                // (b,h) tiles * 2 d-halves

__device__ float g_m1[DI];
__device__ float g_m2[DI];
__device__ float g_partial[NBLK_B];

// ---------------------------------------------------------------------------
// Kernel A: per-column mean / mean-of-square. One block per d.
// For fixed d the data is 16 contiguous 1024-float chunks -> float4 coalesced.
// ---------------------------------------------------------------------------
__global__ void __launch_bounds__(256) colstats_kernel(const float* __restrict__ x) {
    const int d = blockIdx.x;
    const float4* base = (const float4*)(x + (size_t)d * SPATIAL);
    float s1 = 0.f, s2 = 0.f;
    // BB*SPATIAL/4 = 4096 float4s, batch stride DI*SPATIAL/4 float4s
    for (int i = threadIdx.x; i < BB * (SPATIAL / 4); i += 256) {
        const int b = i >> 8;          // / 256
        const int s = i & 255;
        const float4 v = base[(size_t)b * (DI * SPATIAL / 4) + s];
        s1 += v.x + v.y + v.z + v.w;
        s2 += v.x * v.x + v.y * v.y + v.z * v.z + v.w * v.w;
    }
    __shared__ float sh1[256], sh2[256];
    sh1[threadIdx.x] = s1;
    sh2[threadIdx.x] = s2;
    __syncthreads();
    for (int off = 128; off > 0; off >>= 1) {
        if (threadIdx.x < off) {
            sh1[threadIdx.x] += sh1[threadIdx.x + off];
            sh2[threadIdx.x] += sh2[threadIdx.x + off];
        }
        __syncthreads();
    }
    if (threadIdx.x == 0) {
        g_m1[d] = sh1[0] * (1.0f / NN);
        g_m2[d] = sh2[0] * (1.0f / NN);
    }
}

// ---------------------------------------------------------------------------
// Kernel B: fused loss. Tile = one (b,h) pair (32 tokens) x 256 d-columns.
// x slab staged via smem (coalesced float4 global reads, padded-pitch smem).
// mu/lv read as float4 (thread t owns d-cols doff+4t..doff+4t+3, 64 threads
// per w-row cover 256 cols = 1024B contiguous).
// ---------------------------------------------------------------------------
__global__ void __launch_bounds__(256) loss_kernel(const float* __restrict__ x,
                                                   const float* __restrict__ mu,
                                                   const float* __restrict__ lv) {
    const int bh   = blockIdx.x >> 1;   // b*32 + h
    const int dh   = blockIdx.x & 1;
    const int b    = bh >> 5;
    const int h    = bh & 31;
    const int doff = dh * DH;
    const int n0   = bh * WW;

    __shared__ float xs[WW * 260];      // [w*260 + d_local], pad avoids conflicts
    __shared__ float m1s[DH], m2s[DH];

    const int t = threadIdx.x;
    m1s[t] = g_m1[doff + t];
    m2s[t] = g_m2[doff + t];

    // x slab: row d_local has 32 contiguous floats = 8 float4. 256 rows.
    // i over 256*8 float4s: d = i>>3, q = i&7. Warp: fixed d? i>>3 varies within
    // warp (8 lanes per d-row) -> each warp covers 4 d-rows, 128B per row: coalesced.
    const float4* xbase = (const float4*)(x + (size_t)b * (DI * SPATIAL)
                                            + (size_t)doff * SPATIAL
                                            + (size_t)h * WW);
    #pragma unroll 2
    for (int i = t; i < DH * 8; i += 256) {
        const int d = i >> 3;
        const int q = i & 7;
        const float4 v = xbase[(size_t)d * (SPATIAL / 4) + q];
        float* row = &xs[(q * 4) * 260 + d];   // w = q*4 .. q*4+3
        row[0 * 260] = v.x;
        row[1 * 260] = v.y;
        row[2 * 260] = v.z;
        row[3 * 260] = v.w;
    }
    __syncthreads();

    // compute: 256 threads; thread t = (w_group, dq): dq = t & 63 owns 4 cols,
    // wg = t >> 6 owns 8 of the 32 w-rows. Each warp reads 32*16B = 512B contiguous.
    const int dq = t & 63;             // float4 column index within [0,64)
    const int wg = t >> 6;             // 0..3
    const int d0 = dq * 4;             // local d of .x

    const float4 m1v = *(const float4*)&m1s[d0];
    const float4 m2v = *(const float4*)&m2s[d0];

    float acc = 0.f;
    #pragma unroll
    for (int wi = 0; wi < 8; ++wi) {
        const int w = wg * 8 + wi;
        const size_t roff = ((size_t)(n0 + w) * DI + doff) / 4 + dq;
        const float4 m = ((const float4*)mu)[roff];
        const float4 l = ((const float4*)lv)[roff];
        const float* xr = &xs[w * 260 + d0];

        float vx = xr[0], vy = xr[1], vz = xr[2], vw = xr[3];
        acc += (vx * vx - 2.0f * m.x * (vx - m1v.x) - m2v.x) * __expf(-l.x);
        acc += (vy * vy - 2.0f * m.y * (vy - m1v.y) - m2v.y) * __expf(-l.y);
        acc += (vz * vz - 2.0f * m.z * (vz - m1v.z) - m2v.z) * __expf(-l.z);
        acc += (vw * vw - 2.0f * m.w * (vw - m1v.w) - m2v.w) * __expf(-l.w);
    }

    __shared__ float red[256];
    red[t] = acc;
    __syncthreads();
    for (int off = 128; off > 0; off >>= 1) {
        if (t < off) red[t] += red[t + off];
        __syncthreads();
    }
    if (t == 0) g_partial[blockIdx.x] = red[0];
}

// ---------------------------------------------------------------------------
// Kernel C: final reduction -> scalar mean loss.
// ---------------------------------------------------------------------------
__global__ void __launch_bounds__(1024) final_kernel(float* __restrict__ out) {
    const int t = threadIdx.x;
    __shared__ float red[1024];
    red[t] = g_partial[t];
    __syncthreads();
    for (int off = 512; off > 0; off >>= 1) {
        if (t < off) red[t] += red[t + off];
        __syncthreads();
    }
    if (t == 0) out[0] = red[0] * (-0.5f / (float)NN);
}

extern "C" void kernel_launch(void* const* d_in, const int* in_sizes, int n_in,
                              void* d_out, int out_size) {
    const float* x  = (const float*)d_in[0];
    const float* mu = (const float*)d_in[1];
    const float* lv = (const float*)d_in[2];
    float* out = (float*)d_out;

    colstats_kernel<<<DI, 256>>>(x);
    loss_kernel<<<NBLK_B, 256>>>(x, mu, lv);
    final_kernel<<<1, 1024>>>(out);
}

// round 5
// speedup vs baseline: 1.2530x; 1.2530x over previous
#include <cuda_runtime.h>

// CLUBLoss, two-pass (numerically safe per-element cancellation).
//   x        : (B=16, D=512, H=32, W=32) f32
//   p_mu     : (N=16384, D=512) f32,  n = b*H*W + h*W + w
//   p_logvar : (N=16384, D=512) f32
//
// loss_i = -0.5 * sum_d [ (x^2 - m2_d) - 2*mu*(x - m1_d) ] * exp(-lv)
// out    = mean_i loss_i
// m1_d = mean_j x_jd, m2_d = mean_j x_jd^2  (computed in pass 1)

#define DI      512
#define BB      16
#define HH      32
#define WW      32
#define NN      (BB * HH * WW)
#define SPATIAL (HH * WW)
#define DH      256
#define NBLK    1024   // 512 (b,h) tiles * 2 d-halves

__device__ float g_m1[DI];
__device__ float g_m2[DI];
__device__ float g_A;

// ---------------------------------------------------------------------------
// Pass 1: per-column mean / mean-of-square. One block per d.
// For fixed d the data is 16 chunks of 1024 contiguous floats.
// 4096 float4s / 256 threads = exactly 16 per thread, fully unrolled -> MLP 16.
// ---------------------------------------------------------------------------
__global__ void __launch_bounds__(256) colstats_kernel(const float* __restrict__ x) {
    const int d = blockIdx.x;
    const int t = threadIdx.x;
    if (blockIdx.x == 0 && t == 0) g_A = 0.f;   // stream-ordered init for pass 2

    const float4* base = (const float4*)(x + (size_t)d * SPATIAL);
    float s1 = 0.f, s2 = 0.f;
    #pragma unroll
    for (int it = 0; it < 16; ++it) {
        const int i = t + it * 256;              // 0..4095
        const int b = i >> 8;                    // batch
        const int s = i & 255;                   // float4 within 1024-float chunk
        const float4 v = base[(size_t)b * (DI * SPATIAL / 4) + s];
        s1 += v.x + v.y + v.z + v.w;
        s2 += v.x * v.x + v.y * v.y + v.z * v.z + v.w * v.w;
    }
    __shared__ float sh1[256], sh2[256];
    sh1[t] = s1;
    sh2[t] = s2;
    __syncthreads();
    for (int off = 128; off > 0; off >>= 1) {
        if (t < off) {
            sh1[t] += sh1[t + off];
            sh2[t] += sh2[t + off];
        }
        __syncthreads();
    }
    if (t == 0) {
        g_m1[d] = sh1[0] * (1.0f / NN);
        g_m2[d] = sh2[0] * (1.0f / NN);
    }
}

// ---------------------------------------------------------------------------
// Pass 2: fused loss. Block = one (b,h) pair (32 tokens) x 256 d-columns.
// x slab staged via smem (coalesced float4, padded pitch). Thread t owns
// d-quad dq=t&63 and token-group wg=t>>6 (8 tokens), mu/lv batched 2 tokens
// (4 LDG.128 in flight / thread; 48 warps/SM supply the rest of the MLP).
// Per-element cancellation keeps every accumuland O(1) -> fp32-safe.
// ---------------------------------------------------------------------------
__global__ void __launch_bounds__(256, 6) loss_kernel(const float* __restrict__ x,
                                                      const float* __restrict__ mu,
                                                      const float* __restrict__ lv) {
    const int bh   = blockIdx.x >> 1;
    const int dh   = blockIdx.x & 1;
    const int b    = bh >> 5;
    const int h    = bh & 31;
    const int doff = dh * DH;
    const int n0   = bh * WW;

    __shared__ float xs[WW * 260];          // 33280 B
    __shared__ float m1s[DH], m2s[DH];
    float* redA = xs;                       // aliased after compute

    const int t  = threadIdx.x;
    const int dq = t & 63;
    const int wg = t >> 6;
    const int d0 = dq * 4;

    m1s[t] = g_m1[doff + t];
    m2s[t] = g_m2[doff + t];

    // stage x slab: 8 float4 per thread, unrolled
    const float4* xbase = (const float4*)(x + (size_t)b * (DI * SPATIAL)
                                            + (size_t)doff * SPATIAL
                                            + (size_t)h * WW);
    #pragma unroll
    for (int it = 0; it < 8; ++it) {
        const int i = t + it * 256;
        const int d = i >> 3;
        const int q = i & 7;
        const float4 v = xbase[(size_t)d * (SPATIAL / 4) + q];
        float* row = &xs[(q * 4) * 260 + d];
        row[0 * 260] = v.x; row[1 * 260] = v.y;
        row[2 * 260] = v.z; row[3 * 260] = v.w;
    }
    __syncthreads();

    const float4 m1v = *(const float4*)&m1s[d0];
    const float4 m2v = *(const float4*)&m2s[d0];

    float acc = 0.f;
    const size_t rbase = ((size_t)(n0 + wg * 8) * DI + doff) / 4 + dq;

    #pragma unroll
    for (int g = 0; g < 4; ++g) {
        // batch 2 tokens of mu/lv -> 4 LDG.128 in flight
        float4 m0 = ((const float4*)mu)[rbase + (size_t)(g * 2 + 0) * (DI / 4)];
        float4 l0 = ((const float4*)lv)[rbase + (size_t)(g * 2 + 0) * (DI / 4)];
        float4 m1_ = ((const float4*)mu)[rbase + (size_t)(g * 2 + 1) * (DI / 4)];
        float4 l1_ = ((const float4*)lv)[rbase + (size_t)(g * 2 + 1) * (DI / 4)];

        #pragma unroll
        for (int k = 0; k < 2; ++k) {
            const int w = wg * 8 + g * 2 + k;
            const float4 m = k ? m1_ : m0;
            const float4 l = k ? l1_ : l0;
            const float* xr = &xs[w * 260 + d0];
            const float vx = xr[0], vy = xr[1], vz = xr[2], vw = xr[3];
            acc += ((vx * vx - m2v.x) - 2.0f * m.x * (vx - m1v.x)) * __expf(-l.x);
            acc += ((vy * vy - m2v.y) - 2.0f * m.y * (vy - m1v.y)) * __expf(-l.y);
            acc += ((vz * vz - m2v.z) - 2.0f * m.z * (vz - m1v.z)) * __expf(-l.z);
            acc += ((vw * vw - m2v.w) - 2.0f * m.w * (vw - m1v.w)) * __expf(-l.w);
        }
    }

    __syncthreads();       // done reading xs
    redA[t] = acc;
    __syncthreads();
    for (int off = 128; off > 0; off >>= 1) {
        if (t < off) redA[t] += redA[t + off];
        __syncthreads();
    }
    if (t == 0) atomicAdd(&g_A, redA[0]);
}

// ---------------------------------------------------------------------------
__global__ void final_kernel(float* __restrict__ out) {
    out[0] = g_A * (-0.5f / (float)NN);
}

extern "C" void kernel_launch(void* const* d_in, const int* in_sizes, int n_in,
                              void* d_out, int out_size) {
    const float* x  = (const float*)d_in[0];
    const float* mu = (const float*)d_in[1];
    const float* lv = (const float*)d_in[2];
    float* out = (float*)d_out;

    colstats_kernel<<<DI, 256>>>(x);
    loss_kernel<<<NBLK, 256>>>(x, mu, lv);
    final_kernel<<<1, 1>>>(out);
}

// round 6
// speedup vs baseline: 1.2725x; 1.0156x over previous
#include <cuda_runtime.h>

// CLUBLoss, two-pass (numerically safe per-element cancellation).
//   x        : (B=16, D=512, H=32, W=32) f32
//   p_mu     : (N=16384, D=512) f32,  n = b*H*W + h*W + w
//   p_logvar : (N=16384, D=512) f32
//
// loss_i = -0.5 * sum_d [ (x^2 - m2_d) - 2*mu*(x - m1_d) ] * exp(-lv)
// out    = mean_i loss_i
// m1_d = mean_j x_jd, m2_d = mean_j x_jd^2  (pass 1, raw sums via atomics)

#define DI      512
#define BB      16
#define HH      32
#define WW      32
#define NN      (BB * HH * WW)
#define SPATIAL (HH * WW)
#define DH      128
#define NBLK2   2048   // 512 (b,h) tiles * 4 d-quarters

__device__ float g_m1[DI];   // raw column sums (scaled at use site)
__device__ float g_m2[DI];
__device__ float g_A;

// ---------------------------------------------------------------------------
__global__ void __launch_bounds__(512) zero_kernel() {
    const int t = threadIdx.x;
    g_m1[t] = 0.f;
    g_m2[t] = 0.f;
    if (t == 0) g_A = 0.f;
}

// ---------------------------------------------------------------------------
// Pass 1: warp-per-(b,d) pair. Each pair is 1024 contiguous floats (4KB).
// 8192 pairs -> 1024 blocks of 8 warps. 8 LDG.128 in flight per lane.
// Warp-shuffle reduce, then spread-address atomicAdd (16 adds per d).
// ---------------------------------------------------------------------------
__global__ void __launch_bounds__(256) colstats_kernel(const float* __restrict__ x) {
    const int t    = threadIdx.x;
    const int lane = t & 31;
    const int p    = blockIdx.x * 8 + (t >> 5);   // (b,d) pair index, 0..8191
    const int d    = p & 511;

    const float4* base = (const float4*)x + (size_t)p * (SPATIAL / 4);
    float s1 = 0.f, s2 = 0.f;
    #pragma unroll
    for (int k = 0; k < 8; ++k) {
        const float4 v = base[lane + k * 32];
        s1 += v.x + v.y + v.z + v.w;
        s2 += v.x * v.x + v.y * v.y + v.z * v.z + v.w * v.w;
    }
    #pragma unroll
    for (int off = 16; off > 0; off >>= 1) {
        s1 += __shfl_xor_sync(0xffffffffu, s1, off);
        s2 += __shfl_xor_sync(0xffffffffu, s2, off);
    }
    if (lane == 0) {
        atomicAdd(&g_m1[d], s1);
        atomicAdd(&g_m2[d], s2);
    }
}

// ---------------------------------------------------------------------------
// Pass 2: fused loss. Block = one (b,h) pair (32 tokens) x 128 d-columns.
// x slab staged via smem (coalesced float4); thread t owns d-quad dq=t&31
// and 4 tokens (wg=t>>5), with all 8 mu/lv LDG.128 batched -> MLP 8.
// Per-element cancellation keeps every accumuland O(1) -> fp32-safe.
// ---------------------------------------------------------------------------
__global__ void __launch_bounds__(256) loss_kernel(const float* __restrict__ x,
                                                   const float* __restrict__ mu,
                                                   const float* __restrict__ lv) {
    const int bh    = blockIdx.x >> 2;    // b*32 + h
    const int dpart = blockIdx.x & 3;
    const int b     = bh >> 5;
    const int h     = bh & 31;
    const int doff  = dpart * DH;
    const int n0    = bh * WW;

    __shared__ float xs[WW * 132];        // [w*132 + d_local], 16.9 KB
    __shared__ float m1s[DH], m2s[DH];
    float* redA = xs;                     // aliased after compute

    const int t  = threadIdx.x;
    const int dq = t & 31;                // d-quad (4 cols) within tile
    const int wg = t >> 5;                // token group, 4 tokens each
    const int d0 = dq * 4;

    if (t < DH) {
        m1s[t] = g_m1[doff + t] * (1.0f / NN);
        m2s[t] = g_m2[doff + t] * (1.0f / NN);
    }

    // stage x slab: 128 d-rows x 8 float4 = 1024 float4, 4 per thread
    const float4* xbase = (const float4*)(x + (size_t)b * (DI * SPATIAL)
                                            + (size_t)doff * SPATIAL
                                            + (size_t)h * WW);
    #pragma unroll
    for (int it = 0; it < 4; ++it) {
        const int i = t + it * 256;
        const int dr = i >> 3;
        const int q  = i & 7;
        const float4 v = xbase[(size_t)dr * (SPATIAL / 4) + q];
        float* row = &xs[(q * 4) * 132 + dr];
        row[0 * 132] = v.x; row[1 * 132] = v.y;
        row[2 * 132] = v.z; row[3 * 132] = v.w;
    }
    __syncthreads();

    const float4 m1v = *(const float4*)&m1s[d0];
    const float4 m2v = *(const float4*)&m2s[d0];

    // batch all 4 tokens' mu/lv: 8 LDG.128 in flight
    const size_t rbase = ((size_t)(n0 + wg * 4) * DI + doff) / 4 + dq;
    float4 m[4], l[4];
    #pragma unroll
    for (int k = 0; k < 4; ++k) {
        m[k] = ((const float4*)mu)[rbase + (size_t)k * (DI / 4)];
        l[k] = ((const float4*)lv)[rbase + (size_t)k * (DI / 4)];
    }

    float acc = 0.f;
    #pragma unroll
    for (int k = 0; k < 4; ++k) {
        const int w = wg * 4 + k;
        const float* xr = &xs[w * 132 + d0];
        const float vx = xr[0], vy = xr[1], vz = xr[2], vw = xr[3];
        acc += ((vx * vx - m2v.x) - 2.0f * m[k].x * (vx - m1v.x)) * __expf(-l[k].x);
        acc += ((vy * vy - m2v.y) - 2.0f * m[k].y * (vy - m1v.y)) * __expf(-l[k].y);
        acc += ((vz * vz - m2v.z) - 2.0f * m[k].z * (vz - m1v.z)) * __expf(-l[k].z);
        acc += ((vw * vw - m2v.w) - 2.0f * m[k].w * (vw - m1v.w)) * __expf(-l[k].w);
    }

    __syncthreads();     // done reading xs
    redA[t] = acc;
    __syncthreads();
    for (int off = 128; off > 0; off >>= 1) {
        if (t < off) redA[t] += redA[t + off];
        __syncthreads();
    }
    if (t == 0) atomicAdd(&g_A, redA[0]);
}

// ---------------------------------------------------------------------------
__global__ void final_kernel(float* __restrict__ out) {
    out[0] = g_A * (-0.5f / (float)NN);
}

extern "C" void kernel_launch(void* const* d_in, const int* in_sizes, int n_in,
                              void* d_out, int out_size) {
    const float* x  = (const float*)d_in[0];
    const float* mu = (const float*)d_in[1];
    const float* lv = (const float*)d_in[2];
    float* out = (float*)d_out;

    zero_kernel<<<1, 512>>>();
    colstats_kernel<<<1024, 256>>>(x);
    loss_kernel<<<NBLK2, 256>>>(x, mu, lv);
    final_kernel<<<1, 1>>>(out);
}